// round 12
// baseline (speedup 1.0000x reference)
#include <cuda_runtime.h>
#include <math.h>
#include <stdint.h>

// Problem constants (fixed shapes from reference setup_inputs)
#define T_STEPS 512
#define BATCH   128
#define MDIM    31
#define HID     512
#define EMB     256
#define SDIM    128
#define G3      (3*HID)          // 1536
#define TB      (T_STEPS*BATCH)  // 65536
#define BH      (BATCH*HID)      // 65536

#define SIGMA_MIN 0.01f
#define GAMMA     1.0f
#define LOG2PI    1.8378770664093453f

typedef unsigned long long ull;

// Scratch (device globals: no allocations allowed)
__device__ float g_phi[TB*EMB];                 //  67 MB
__device__ float g_xg [(size_t)TB*G3];          // 402 MB
__device__ float g_hs [(size_t)TB*HID];         // 134 MB  (hs[t] = h_t; hs[0]=0)
__device__ float g_loss[TB];                    // per-(t,b) loss, t>=1 written

// per-group barrier state (8 groups, 128B apart; self-resetting across replays)
__device__ unsigned          g_gcnt[8*32];
__device__ volatile unsigned g_ggen[8*32];

__device__ __forceinline__ float sigmoidf_(float v) {
    return 1.0f / (1.0f + expf(-v));
}

// packed fp32x2 ops (Blackwell f32x2 pipe)
__device__ __forceinline__ ull ffma2_(ull a, ull b, ull c) {
    ull d;
    asm("fma.rn.f32x2 %0, %1, %2, %3;" : "=l"(d) : "l"(a), "l"(b), "l"(c));
    return d;
}

__device__ __forceinline__ void cp_async16(uint32_t dst, const void* src) {
    asm volatile("cp.async.ca.shared.global [%0], [%1], 16;" :: "r"(dst), "l"(src));
}

// ---------------------------------------------------------------------------
// Kernel 0: zero h_0
// ---------------------------------------------------------------------------
__global__ void zero_h0_kernel() {
    int i = blockIdx.x * blockDim.x + threadIdx.x;
    if (i < BH) g_hs[i] = 0.0f;
}

// ---------------------------------------------------------------------------
// Kernel 1: phi = relu(x @ W_embed^T + b_embed)   [TB,31] -> [TB,256]
// ---------------------------------------------------------------------------
__global__ void phi_kernel(const float* __restrict__ x,
                           const float* __restrict__ W_embed,
                           const float* __restrict__ b_embed) {
    __shared__ float Ws[EMB * MDIM];
    __shared__ float Xs[16 * MDIM];

    const int tid  = threadIdx.x;      // 256 threads
    const int row0 = blockIdx.x * 16;

    for (int i = tid; i < EMB * MDIM; i += 256) Ws[i] = W_embed[i];
    for (int i = tid; i < 16 * MDIM;  i += 256) Xs[i] = x[row0 * MDIM + i];
    __syncthreads();

    const int e = tid;
    const float be = b_embed[e];
    #pragma unroll 4
    for (int r = 0; r < 16; ++r) {
        float acc = be;
        #pragma unroll
        for (int k = 0; k < MDIM; ++k)
            acc += Xs[r * MDIM + k] * Ws[e * MDIM + k];
        g_phi[(row0 + r) * EMB + e] = fmaxf(acc, 0.0f);
    }
}

// ---------------------------------------------------------------------------
// Kernel 2: x_gates = phi @ W_ih^T + b_ih   [TB,256] x [1536,256] -> [TB,1536]
// 128x128x16 tile, 256 threads, 8x8 microtile, packed f32x2 FMAs (k-pairs).
// ---------------------------------------------------------------------------
__global__ __launch_bounds__(256, 1)
void xg_kernel(const float* __restrict__ W_ih,
               const float* __restrict__ b_ih) {
    __shared__ float As[128][18];      // phi rows (M), k-major, padded
    __shared__ float Bs[128][18];      // W_ih rows (N), k-major, padded

    const int tid = threadIdx.x;       // 256
    const int tx = tid & 15;
    const int ty = tid >> 4;
    const int n0 = blockIdx.x * 128;   // over G3 (12 tiles)
    const int m0 = blockIdx.y * 128;   // over TB (512 tiles)

    ull c2[8][8];
    #pragma unroll
    for (int i = 0; i < 8; ++i)
        #pragma unroll
        for (int j = 0; j < 8; ++j) c2[i][j] = 0ull;

    for (int kc = 0; kc < EMB; kc += 16) {
        #pragma unroll
        for (int v = 0; v < 2; ++v) {
            const int idx = tid + v * 256;       // 0..511
            const int row = idx >> 2;
            const int col = (idx & 3) * 4;
            float4 a = *reinterpret_cast<const float4*>(
                &g_phi[(size_t)(m0 + row) * EMB + kc + col]);
            float4 b = *reinterpret_cast<const float4*>(
                &W_ih[(size_t)(n0 + row) * EMB + kc + col]);
            As[row][col+0] = a.x; As[row][col+1] = a.y;
            As[row][col+2] = a.z; As[row][col+3] = a.w;
            Bs[row][col+0] = b.x; Bs[row][col+1] = b.y;
            Bs[row][col+2] = b.z; Bs[row][col+3] = b.w;
        }
        __syncthreads();

        #pragma unroll
        for (int kp = 0; kp < 8; ++kp) {
            ull a[8], b[8];
            #pragma unroll
            for (int i = 0; i < 8; ++i)
                a[i] = *reinterpret_cast<const ull*>(&As[ty*8 + i][2*kp]);
            #pragma unroll
            for (int j = 0; j < 8; ++j)
                b[j] = *reinterpret_cast<const ull*>(&Bs[tx*8 + j][2*kp]);
            #pragma unroll
            for (int i = 0; i < 8; ++i)
                #pragma unroll
                for (int j = 0; j < 8; ++j)
                    c2[i][j] = ffma2_(a[i], b[j], c2[i][j]);
        }
        __syncthreads();
    }

    // Epilogue: collapse k-pair lanes, add bias, store
    float bias[8];
    #pragma unroll
    for (int j = 0; j < 8; ++j) bias[j] = b_ih[n0 + tx*8 + j];

    #pragma unroll
    for (int i = 0; i < 8; ++i) {
        const int m = m0 + ty*8 + i;
        float v[8];
        #pragma unroll
        for (int j = 0; j < 8; ++j) {
            union { ull u; float2 f; } u; u.u = c2[i][j];
            v[j] = u.f.x + u.f.y + bias[j];
        }
        float4* dst = reinterpret_cast<float4*>(&g_xg[(size_t)m * G3 + n0 + tx*8]);
        dst[0] = make_float4(v[0], v[1], v[2], v[3]);
        dst[1] = make_float4(v[4], v[5], v[6], v[7]);
    }
}

// ---------------------------------------------------------------------------
// Kernel 3: PERSISTENT GRU, 2-D split. 128 CTAs = 16 jg x 8 bg.
// CTA (jg,bg): owns j in [32*jg, 32*jg+32) (x3 gates = 96 W rows, 192 KB in
// smem, loaded ONCE) and batch rows [16*bg, 16*bg+16). Per step it loads only
// its 16x512 h-slice (32 KB, one cp.async burst), computes the 96x16x512
// gate GEMM with 4-way k-split FFMA2 register tiles, reconciles through an
// smem Racc that ALIASES the dead h buffer, applies the gate nonlinearity
// and writes its 16x32 h_{t+1} patch. 8 independent 16-CTA barriers.
//
// W smem layout: row-stride 512 (aligned!), k-pair XOR swizzle:
//   phys(row,k) = row*512 + 2*((k>>1) ^ ((row>>1)&15)) + (k&1)
// Inner loop reads W at offset ks*128 + 2*(kpl ^ jj): all 16 jj of a warp hit
// all 32 banks exactly once (conflict-free, 8B-aligned), 2-way bb broadcast.
// H pad 516: the two bb row-groups sit 4 banks apart -> conflict-free.
// Threads 256: tid = ks*64 + bb*16 + jj  (ks: k-quarter, bb: 4 b-rows, jj: 2 j)
// ---------------------------------------------------------------------------
#define PADH 516       // even (8B ok), 516*4 % 16 == 0 (cp.async16 ok), mod 32 = 4 banks
#define W_FLOATS (96*512)                  // 49152 floats = 196608 B
#define H_FLOATS (16*PADH)                 // 8256 floats  =  33024 B
#define GRU_SMEM_BYTES ((W_FLOATS + H_FLOATS)*4)   // 229632

__device__ __forceinline__ void group_barrier_(int grp) {
    __syncthreads();
    if (threadIdx.x == 0) {
        const int slot = grp * 32;
        unsigned gen = g_ggen[slot];
        __threadfence();
        if (atomicAdd(&g_gcnt[slot], 1u) == 15u) {
            g_gcnt[slot] = 0;
            __threadfence();
            g_ggen[slot] = gen + 1;
        } else {
            while (g_ggen[slot] == gen) {}
            __threadfence();
        }
    }
    __syncthreads();
}

__global__ __launch_bounds__(256, 1)
void gru_persistent_kernel(const float* __restrict__ W_hh,
                           const float* __restrict__ b_hh) {
    extern __shared__ float smem[];
    float* Ws = smem;                  // [96][512], k-pair swizzled
    float* Hs = smem + W_FLOATS;       // [16][PADH]
    float* Racc = Hs;                  // aliases Hs: [256][25] floats (25600B)

    const int tid = threadIdx.x;
    const int bg  = blockIdx.x >> 4;   // 0..7   batch group
    const int jg  = blockIdx.x & 15;   // 0..15  j group

    // compute mapping
    const int ks = tid >> 6;           // k-quarter
    const int bb = (tid >> 4) & 3;     // 4 b-rows: bb*4 .. bb*4+3
    const int jj = tid & 15;           // 2 j-cols: jj*2, jj*2+1

    // epilogue mapping: 2 outputs per thread: (eb, ejj*2+{0,1})
    const int eb  = tid >> 4;          // 0..15 local batch row
    const int ejj = tid & 15;

    // Load this CTA's W_hh slice once (swizzled layout).
    // smem row wr = g*32 + jl; phys float offset:
    //   wr*512 + 2*((k>>1) ^ ((wr>>1)&15)) + (k&1)
    for (int i = tid; i < 96 * HID; i += 256) {
        const int wr = i >> 9, k = i & (HID - 1);
        const int g = wr >> 5, jl = wr & 31;
        const int swz = (wr >> 1) & 15;
        const int phys = wr * 512 + 2 * ((k >> 1) ^ swz) + (k & 1);
        Ws[phys] = W_hh[((size_t)(g * HID + jg * 32 + jl)) * HID + k];
    }

    // epilogue biases for this thread's two j columns
    const int j0 = jg * 32 + ejj * 2;
    const float bh_r0 = b_hh[j0],           bh_r1 = b_hh[j0 + 1];
    const float bh_z0 = b_hh[HID + j0],     bh_z1 = b_hh[HID + j0 + 1];
    const float bh_n0 = b_hh[2*HID + j0],   bh_n1 = b_hh[2*HID + j0 + 1];
    const int gb = bg * 16 + eb;       // global batch row for epilogue
    __syncthreads();

    const uint32_t hs_base = (uint32_t)__cvta_generic_to_shared(Hs);
    const int cr  = tid >> 4;          // copy: row 0..15
    const int cc  = tid & 15;          // copy: 16B chunk phase

    // inner-loop base pointers (thread-invariant parts)
    const float* Wbase = Ws + (jj * 2) * 512 + ks * 128;   // + 2*(kpl^jj) at use
    const float* Hbase = Hs + bb * 4 * PADH + ks * 128;    // + 2*kpl at use

    for (int t = 0; t < T_STEPS - 1; ++t) {
        const float* __restrict__ hsrc = g_hs + (size_t)t * BH;
        float*       __restrict__ hdst = g_hs + (size_t)(t + 1) * BH;
        const float* __restrict__ xg   = g_xg + (size_t)t * BATCH * G3;

        // Prefetch epilogue operands (in flight under the h-load + GEMM)
        const float xr0 = xg[(size_t)gb * G3 + j0];
        const float xr1 = xg[(size_t)gb * G3 + j0 + 1];
        const float xz0 = xg[(size_t)gb * G3 + HID + j0];
        const float xz1 = xg[(size_t)gb * G3 + HID + j0 + 1];
        const float xn0 = xg[(size_t)gb * G3 + 2*HID + j0];
        const float xn1 = xg[(size_t)gb * G3 + 2*HID + j0 + 1];
        const float hp0 = hsrc[(size_t)gb * HID + j0];
        const float hp1 = hsrc[(size_t)gb * HID + j0 + 1];

        // Load the 16x512 h-slice for this bg (32 KB, 8x cp.async16/thread)
        {
            const float* src = hsrc + (size_t)(bg * 16 + cr) * HID + cc * 4;
            uint32_t dst = hs_base + (uint32_t)(cr * PADH + cc * 4) * 4u;
            #pragma unroll
            for (int it = 0; it < 8; ++it) {
                cp_async16(dst, src);
                src += 64;
                dst += 256;
            }
            asm volatile("cp.async.commit_group;");
        }

        ull acc[3][4][2];
        #pragma unroll
        for (int g = 0; g < 3; ++g)
            #pragma unroll
            for (int i = 0; i < 4; ++i) { acc[g][i][0] = 0ull; acc[g][i][1] = 0ull; }

        asm volatile("cp.async.wait_group 0;");
        __syncthreads();

        // GEMM: 4 b-rows x 2 j x 3 gates over k-quarter [ks*128, +128)
        #pragma unroll 8
        for (int kpl = 0; kpl < 64; ++kpl) {
            const int kk   = 2 * kpl;            // H logical offset
            const int koff = 2 * (kpl ^ jj);     // W swizzled offset
            ull h[4];
            #pragma unroll
            for (int i = 0; i < 4; ++i)
                h[i] = *reinterpret_cast<const ull*>(Hbase + i * PADH + kk);
            #pragma unroll
            for (int g = 0; g < 3; ++g) {
                const ull w0 = *reinterpret_cast<const ull*>(Wbase + (g*32    )*512 + koff);
                const ull w1 = *reinterpret_cast<const ull*>(Wbase + (g*32 + 1)*512 + koff);
                #pragma unroll
                for (int i = 0; i < 4; ++i) {
                    acc[g][i][0] = ffma2_(h[i], w0, acc[g][i][0]);
                    acc[g][i][1] = ffma2_(h[i], w1, acc[g][i][1]);
                }
            }
        }
        __syncthreads();   // h reads done; Hs region now reusable as Racc

        // Publish collapsed partials: Racc[tid][ (i*2+o)*3+g ]
        {
            float* R = Racc + tid * 25;
            #pragma unroll
            for (int i = 0; i < 4; ++i)
                #pragma unroll
                for (int o = 0; o < 2; ++o)
                    #pragma unroll
                    for (int g = 0; g < 3; ++g) {
                        union { ull u; float2 f; } u; u.u = acc[g][i][o];
                        R[(i*2 + o)*3 + g] = u.f.x + u.f.y;
                    }
        }
        __syncthreads();

        // Reconcile 4 k-split partials and apply gate nonlinearity
        float hg[2][3];
        #pragma unroll
        for (int o = 0; o < 2; ++o)
            #pragma unroll
            for (int g = 0; g < 3; ++g) {
                const int slot = ((eb & 3)*2 + o)*3 + g;
                const int base = ((eb >> 2)*16 + ejj)*25 + slot;
                hg[o][g] = Racc[(0*64)*25 + base] + Racc[(1*64)*25 + base]
                         + Racc[(2*64)*25 + base] + Racc[(3*64)*25 + base];
            }

        {
            const float r = sigmoidf_(xr0 + hg[0][0] + bh_r0);
            const float z = sigmoidf_(xz0 + hg[0][1] + bh_z0);
            const float n = tanhf(xn0 + r * (hg[0][2] + bh_n0));
            hdst[(size_t)gb * HID + j0] = (1.0f - z) * n + z * hp0;
        }
        {
            const float r = sigmoidf_(xr1 + hg[1][0] + bh_r1);
            const float z = sigmoidf_(xz1 + hg[1][1] + bh_z1);
            const float n = tanhf(xn1 + r * (hg[1][2] + bh_n1));
            hdst[(size_t)gb * HID + j0 + 1] = (1.0f - z) * n + z * hp1;
        }

        group_barrier_(bg);
    }
}

// ---------------------------------------------------------------------------
// Kernel 4: per-(t,b) loss for t>=1.
// ---------------------------------------------------------------------------
__global__ void loss_kernel(const float* __restrict__ x,
                            const float* __restrict__ tin,
                            const float* __restrict__ mask,
                            const float* __restrict__ W_he,
                            const float* __restrict__ b_he,
                            const float* __restrict__ W_mu,
                            const float* __restrict__ b_mu,
                            const float* __restrict__ W_lv,
                            const float* __restrict__ b_lv,
                            const float* __restrict__ h_inf,
                            const float* __restrict__ t_inf,
                            const float* __restrict__ b_int) {
    __shared__ float Hs[8][HID];
    __shared__ float Ws[SDIM][17];
    __shared__ float He[8][SDIM];
    __shared__ float red[8][32];

    const int tid    = threadIdx.x;    // 256
    const int r_base = BATCH + blockIdx.x * 8;

    for (int i = tid; i < 8 * HID; i += 256) {
        int rr = i >> 9, k = i & (HID - 1);
        Hs[rr][k] = g_hs[(size_t)(r_base + rr) * HID + k];
    }
    __syncthreads();

    const int s    = tid & 127;
    const int rgrp = tid >> 7;
    float acc[4] = {0.f, 0.f, 0.f, 0.f};

    for (int kc = 0; kc < HID; kc += 16) {
        for (int i = tid; i < SDIM * 16; i += 256) {
            int s2 = i >> 4, k = i & 15;
            Ws[s2][k] = W_he[(size_t)s2 * HID + kc + k];
        }
        __syncthreads();
        #pragma unroll
        for (int k = 0; k < 16; ++k) {
            float w = Ws[s][k];
            #pragma unroll
            for (int q = 0; q < 4; ++q)
                acc[q] += Hs[rgrp + 2*q][kc + k] * w;
        }
        __syncthreads();
    }
    {
        const float bs = b_he[s];
        #pragma unroll
        for (int q = 0; q < 4; ++q)
            He[rgrp + 2*q][s] = fmaxf(acc[q] + bs, 0.0f);
    }
    __syncthreads();

    if (tid < 8 * MDIM) {
        const int r = tid / MDIM;
        const int m = tid % MDIM;
        float mu = b_mu[m];
        float lv = b_lv[m];
        #pragma unroll 4
        for (int k = 0; k < SDIM; ++k) {
            const float he = He[r][k];
            mu += W_mu[m * SDIM + k] * he;
            lv += W_lv[m * SDIM + k] * he;
        }
        const float sigma = fmaxf(expf(0.5f * lv), SIGMA_MIN);
        const float xv = x[(size_t)(r_base + r) * MDIM + m];
        const float d = (xv - mu) / sigma;
        red[r][m] = -0.5f * d * d - logf(sigma) - 0.5f * LOG2PI;
    }
    __syncthreads();

    if (tid < 8) {
        const int r = tid;
        float marker_ll = 0.0f;
        for (int m = 0; m < MDIM; ++m) marker_ll += red[r][m];

        float past = 0.0f;
        for (int k = 0; k < SDIM; ++k) past += He[r][k] * h_inf[k];

        const float ti = t_inf[0];
        const float bi = b_int[0];
        const float tg = tin[(size_t)(r_base + r) * 2 + 1];
        const float term1 = past + ti * tg + bi;
        const float time_ll = term1 + (expf(past + bi) - expf(term1)) / ti;

        const int row = r_base + r;
        g_loss[row] = (GAMMA * (-time_ll) + (-marker_ll)) * mask[row];
    }
}

// ---------------------------------------------------------------------------
// Kernel 5: deterministic final reduction (double accumulation)
// ---------------------------------------------------------------------------
__global__ void reduce_kernel(float* __restrict__ out) {
    __shared__ double sd[256];
    const int tid = threadIdx.x;
    double sum = 0.0;
    for (int i = BATCH + tid; i < TB; i += 256) sum += (double)g_loss[i];
    sd[tid] = sum;
    __syncthreads();
    for (int off = 128; off > 0; off >>= 1) {
        if (tid < off) sd[tid] += sd[tid + off];
        __syncthreads();
    }
    if (tid == 0) out[0] = (float)sd[0];
}

// ---------------------------------------------------------------------------
extern "C" void kernel_launch(void* const* d_in, const int* in_sizes, int n_in,
                              void* d_out, int out_size) {
    (void)in_sizes; (void)n_in; (void)out_size;
    const float* x       = (const float*)d_in[0];
    const float* tin     = (const float*)d_in[1];
    const float* mask    = (const float*)d_in[2];
    const float* W_embed = (const float*)d_in[3];
    const float* b_embed = (const float*)d_in[4];
    const float* W_ih    = (const float*)d_in[5];
    const float* b_ih    = (const float*)d_in[6];
    const float* W_hh    = (const float*)d_in[7];
    const float* b_hh    = (const float*)d_in[8];
    const float* W_he    = (const float*)d_in[9];
    const float* b_he    = (const float*)d_in[10];
    const float* W_mu    = (const float*)d_in[11];
    const float* b_mu    = (const float*)d_in[12];
    const float* W_lv    = (const float*)d_in[13];
    const float* b_lv    = (const float*)d_in[14];
    const float* h_inf   = (const float*)d_in[15];
    const float* t_inf   = (const float*)d_in[16];
    const float* b_int   = (const float*)d_in[17];
    float* out = (float*)d_out;

    cudaFuncSetAttribute(gru_persistent_kernel,
                         cudaFuncAttributeMaxDynamicSharedMemorySize,
                         GRU_SMEM_BYTES);

    zero_h0_kernel<<<64, 1024>>>();
    phi_kernel<<<TB / 16, 256>>>(x, W_embed, b_embed);
    xg_kernel<<<dim3(G3 / 128, TB / 128), 256>>>(W_ih, b_ih);
    gru_persistent_kernel<<<128, 256, GRU_SMEM_BYTES>>>(W_hh, b_hh);
    loss_kernel<<<(TB - BATCH) / 8, 256>>>(x, tin, mask, W_he, b_he,
                                           W_mu, b_mu, W_lv, b_lv,
                                           h_inf, t_inf, b_int);
    reduce_kernel<<<1, 256>>>(out);
}

// round 13
// speedup vs baseline: 1.5558x; 1.5558x over previous
#include <cuda_runtime.h>
#include <math.h>
#include <stdint.h>

// Problem constants (fixed shapes from reference setup_inputs)
#define T_STEPS 512
#define BATCH   128
#define MDIM    31
#define HID     512
#define EMB     256
#define SDIM    128
#define G3      (3*HID)          // 1536
#define TB      (T_STEPS*BATCH)  // 65536
#define BH      (BATCH*HID)      // 65536

#define SIGMA_MIN 0.01f
#define GAMMA     1.0f
#define LOG2PI    1.8378770664093453f

typedef unsigned long long ull;

// Scratch (device globals: no allocations allowed)
__device__ float g_phi[TB*EMB];                 //  67 MB
__device__ float g_xg [(size_t)TB*G3];          // 402 MB
__device__ float g_hs [(size_t)TB*HID];         // 134 MB  (hs[t] = h_t; hs[0]=0)
__device__ float g_loss[TB];                    // per-(t,b) loss, t>=1 written
__device__ double g_partial[64];                // reduction partials

// per-group barrier state (8 groups, 128B apart; self-resetting across replays)
__device__ unsigned          g_gcnt[8*32];
__device__ volatile unsigned g_ggen[8*32];

__device__ __forceinline__ float sigmoidf_(float v) {
    return 1.0f / (1.0f + expf(-v));
}

// packed fp32x2 ops (Blackwell f32x2 pipe)
__device__ __forceinline__ ull ffma2_(ull a, ull b, ull c) {
    ull d;
    asm("fma.rn.f32x2 %0, %1, %2, %3;" : "=l"(d) : "l"(a), "l"(b), "l"(c));
    return d;
}

__device__ __forceinline__ void cp_async16(uint32_t dst, const void* src) {
    asm volatile("cp.async.ca.shared.global [%0], [%1], 16;" :: "r"(dst), "l"(src));
}

// ---------------------------------------------------------------------------
// Kernel 0: zero h_0
// ---------------------------------------------------------------------------
__global__ void zero_h0_kernel() {
    int i = blockIdx.x * blockDim.x + threadIdx.x;
    if (i < BH) g_hs[i] = 0.0f;
}

// ---------------------------------------------------------------------------
// Kernel 1: phi = relu(x @ W_embed^T + b_embed)   [TB,31] -> [TB,256]
// ---------------------------------------------------------------------------
__global__ void phi_kernel(const float* __restrict__ x,
                           const float* __restrict__ W_embed,
                           const float* __restrict__ b_embed) {
    __shared__ float Ws[EMB * MDIM];
    __shared__ float Xs[16 * MDIM];

    const int tid  = threadIdx.x;      // 256 threads
    const int row0 = blockIdx.x * 16;

    for (int i = tid; i < EMB * MDIM; i += 256) Ws[i] = W_embed[i];
    for (int i = tid; i < 16 * MDIM;  i += 256) Xs[i] = x[row0 * MDIM + i];
    __syncthreads();

    const int e = tid;
    const float be = b_embed[e];
    #pragma unroll 4
    for (int r = 0; r < 16; ++r) {
        float acc = be;
        #pragma unroll
        for (int k = 0; k < MDIM; ++k)
            acc += Xs[r * MDIM + k] * Ws[e * MDIM + k];
        g_phi[(row0 + r) * EMB + e] = fmaxf(acc, 0.0f);
    }
}

// ---------------------------------------------------------------------------
// Kernel 2: x_gates = phi @ W_ih^T + b_ih   [TB,256] x [1536,256] -> [TB,1536]
// 128x128x16 tile, 256 threads, 8x8 microtile, packed f32x2 FMAs (k-pairs).
// ---------------------------------------------------------------------------
__global__ __launch_bounds__(256, 1)
void xg_kernel(const float* __restrict__ W_ih,
               const float* __restrict__ b_ih) {
    __shared__ float As[128][18];      // phi rows (M), k-major, padded
    __shared__ float Bs[128][18];      // W_ih rows (N), k-major, padded

    const int tid = threadIdx.x;       // 256
    const int tx = tid & 15;
    const int ty = tid >> 4;
    const int n0 = blockIdx.x * 128;   // over G3 (12 tiles)
    const int m0 = blockIdx.y * 128;   // over TB (512 tiles)

    ull c2[8][8];
    #pragma unroll
    for (int i = 0; i < 8; ++i)
        #pragma unroll
        for (int j = 0; j < 8; ++j) c2[i][j] = 0ull;

    for (int kc = 0; kc < EMB; kc += 16) {
        #pragma unroll
        for (int v = 0; v < 2; ++v) {
            const int idx = tid + v * 256;       // 0..511
            const int row = idx >> 2;
            const int col = (idx & 3) * 4;
            float4 a = *reinterpret_cast<const float4*>(
                &g_phi[(size_t)(m0 + row) * EMB + kc + col]);
            float4 b = *reinterpret_cast<const float4*>(
                &W_ih[(size_t)(n0 + row) * EMB + kc + col]);
            As[row][col+0] = a.x; As[row][col+1] = a.y;
            As[row][col+2] = a.z; As[row][col+3] = a.w;
            Bs[row][col+0] = b.x; Bs[row][col+1] = b.y;
            Bs[row][col+2] = b.z; Bs[row][col+3] = b.w;
        }
        __syncthreads();

        #pragma unroll
        for (int kp = 0; kp < 8; ++kp) {
            ull a[8], b[8];
            #pragma unroll
            for (int i = 0; i < 8; ++i)
                a[i] = *reinterpret_cast<const ull*>(&As[ty*8 + i][2*kp]);
            #pragma unroll
            for (int j = 0; j < 8; ++j)
                b[j] = *reinterpret_cast<const ull*>(&Bs[tx*8 + j][2*kp]);
            #pragma unroll
            for (int i = 0; i < 8; ++i)
                #pragma unroll
                for (int j = 0; j < 8; ++j)
                    c2[i][j] = ffma2_(a[i], b[j], c2[i][j]);
        }
        __syncthreads();
    }

    // Epilogue: collapse k-pair lanes, add bias, store
    float bias[8];
    #pragma unroll
    for (int j = 0; j < 8; ++j) bias[j] = b_ih[n0 + tx*8 + j];

    #pragma unroll
    for (int i = 0; i < 8; ++i) {
        const int m = m0 + ty*8 + i;
        float v[8];
        #pragma unroll
        for (int j = 0; j < 8; ++j) {
            union { ull u; float2 f; } u; u.u = c2[i][j];
            v[j] = u.f.x + u.f.y + bias[j];
        }
        float4* dst = reinterpret_cast<float4*>(&g_xg[(size_t)m * G3 + n0 + tx*8]);
        dst[0] = make_float4(v[0], v[1], v[2], v[3]);
        dst[1] = make_float4(v[4], v[5], v[6], v[7]);
    }
}

// ---------------------------------------------------------------------------
// Kernel 3: PERSISTENT GRU, 2-D split, 512 threads (4 warps/SMSP).
// 128 CTAs = 16 jg x 8 bg. CTA (jg,bg): j in [32*jg,+32) x3 gates (96 W rows,
// 192 KB smem, loaded once, XOR-swizzled) and batch rows [16*bg,+16).
// Per step: 32 KB h-slice via cp.async16, then a 96x16x512 GEMM with 8-way
// k-split FFMA2 register tiles. Thread tid: lane = ksl*16+jj, warp = ksh*4+bb.
// k-split pairs (ksl) live in the same warp -> shfl_xor(16) pair-reduce; the
// remaining 4 partials (ksh) go through an smem Racc (24.6 KB) that ALIASES
// the dead h buffer. Epilogue: 1 output/thread, coalesced. 8 independent
// 16-CTA barriers between steps.
// W swizzle: phys(row,k) = row*512 + 2*((k>>1)^((row>>1)&15)) + (k&1)
//   -> every LDS.64 is 8B-aligned and conflict-free per half-warp.
// ---------------------------------------------------------------------------
#define PADH 516       // even (8B ok), 516*4 % 16 == 0 (cp.async16 ok)
#define W_FLOATS (96*512)                  // 49152 floats = 196608 B
#define H_FLOATS (16*PADH)                 // 8256 floats  =  33024 B
#define GRU_SMEM_BYTES ((W_FLOATS + H_FLOATS)*4)   // 229632

__device__ __forceinline__ void group_barrier_(int grp) {
    __syncthreads();
    if (threadIdx.x == 0) {
        const int slot = grp * 32;
        unsigned gen = g_ggen[slot];
        __threadfence();
        if (atomicAdd(&g_gcnt[slot], 1u) == 15u) {
            g_gcnt[slot] = 0;
            __threadfence();
            g_ggen[slot] = gen + 1;
        } else {
            while (g_ggen[slot] == gen) {}
            __threadfence();
        }
    }
    __syncthreads();
}

__global__ __launch_bounds__(512, 1)
void gru_persistent_kernel(const float* __restrict__ W_hh,
                           const float* __restrict__ b_hh) {
    extern __shared__ float smem[];
    float* Ws = smem;                  // [96][512], k-pair swizzled
    float* Hs = smem + W_FLOATS;       // [16][PADH]
    float* Racc = Hs;                  // aliases Hs: 16w x 16jj x 24 floats

    const int tid  = threadIdx.x;      // 512
    const int lane = tid & 31;
    const int warp = tid >> 5;         // 0..15
    const int bg   = blockIdx.x >> 4;  // 0..7   batch group
    const int jg   = blockIdx.x & 15;  // 0..15  j group

    // compute mapping
    const int jj  = lane & 15;         // j pair: cols jj*2, jj*2+1
    const int ksl = lane >> 4;         // low k-split bit (in-warp)
    const int bb  = warp & 3;          // 4 b-rows: bb*4 .. bb*4+3
    const int ksh = warp >> 2;         // high k-split bits
    const int ks  = ksh * 2 + ksl;     // 0..7, k-range [ks*64, +64) = 32 kp

    // epilogue mapping: 1 output per thread
    const int eb  = tid >> 5;          // local batch row 0..15
    const int col = tid & 31;          // local j col 0..31
    const int j   = jg * 32 + col;
    const int gb  = bg * 16 + eb;

    // Load this CTA's W_hh slice once (swizzled layout).
    for (int i = tid; i < 96 * HID; i += 512) {
        const int wr = i >> 9, k = i & (HID - 1);
        const int g = wr >> 5, jl = wr & 31;
        const int swz = (wr >> 1) & 15;
        const int phys = wr * 512 + 2 * ((k >> 1) ^ swz) + (k & 1);
        Ws[phys] = W_hh[((size_t)(g * HID + jg * 32 + jl)) * HID + k];
    }

    const float bhr = b_hh[j];
    const float bhz = b_hh[HID + j];
    const float bhn = b_hh[2*HID + j];
    __syncthreads();

    const uint32_t hs_base = (uint32_t)__cvta_generic_to_shared(Hs);
    const int cr = tid >> 5;           // copy: row 0..15
    const int cc = tid & 31;           // copy: 16B chunk phase (32/row-pass)

    // inner-loop thread-invariant base pointers
    const float* Hbase = Hs + bb * 4 * PADH + ks * 64;     // + 2*kpl at use
    const float* Wbase = Ws + (jj * 2) * 512 + ks * 64;    // + 2*(kpl^jj) at use

    for (int t = 0; t < T_STEPS - 1; ++t) {
        const float* __restrict__ hsrc = g_hs + (size_t)t * BH;
        float*       __restrict__ hdst = g_hs + (size_t)(t + 1) * BH;
        const float* __restrict__ xg   = g_xg + (size_t)t * BATCH * G3;

        // Prefetch epilogue operands (coalesced; in flight under h-load+GEMM)
        const float xr = xg[(size_t)gb * G3 + j];
        const float xz = xg[(size_t)gb * G3 + HID + j];
        const float xn = xg[(size_t)gb * G3 + 2*HID + j];
        const float hp = hsrc[(size_t)gb * HID + j];

        // Load the 16x512 h-slice for this bg (32 KB, 4x cp.async16/thread)
        {
            const float* src = hsrc + (size_t)(bg * 16 + cr) * HID + cc * 4;
            uint32_t dst = hs_base + (uint32_t)(cr * PADH + cc * 4) * 4u;
            #pragma unroll
            for (int it = 0; it < 4; ++it) {
                cp_async16(dst, src);
                src += 128;
                dst += 512;
            }
            asm volatile("cp.async.commit_group;");
        }

        ull acc[3][4][2];
        #pragma unroll
        for (int g = 0; g < 3; ++g)
            #pragma unroll
            for (int i = 0; i < 4; ++i) { acc[g][i][0] = 0ull; acc[g][i][1] = 0ull; }

        asm volatile("cp.async.wait_group 0;");
        __syncthreads();

        // GEMM: 4 b-rows x 2 j x 3 gates over k-range [ks*64, +64) (32 kp)
        #pragma unroll 8
        for (int kpl = 0; kpl < 32; ++kpl) {
            const int kk   = 2 * kpl;            // H logical offset
            const int koff = 2 * (kpl ^ jj);     // W swizzled offset
            ull h[4];
            #pragma unroll
            for (int i = 0; i < 4; ++i)
                h[i] = *reinterpret_cast<const ull*>(Hbase + i * PADH + kk);
            #pragma unroll
            for (int g = 0; g < 3; ++g) {
                const ull w0 = *reinterpret_cast<const ull*>(Wbase + (g*32    )*512 + koff);
                const ull w1 = *reinterpret_cast<const ull*>(Wbase + (g*32 + 1)*512 + koff);
                #pragma unroll
                for (int i = 0; i < 4; ++i) {
                    acc[g][i][0] = ffma2_(h[i], w0, acc[g][i][0]);
                    acc[g][i][1] = ffma2_(h[i], w1, acc[g][i][1]);
                }
            }
        }
        __syncthreads();   // h reads done; Hs region now reusable as Racc

        // Collapse f32x2 lanes, reduce the in-warp ksl pair via shfl_xor(16),
        // publish from lanes < 16. Slot order: (g*4+i)*2+o.
        {
            float p[24];
            #pragma unroll
            for (int g = 0; g < 3; ++g)
                #pragma unroll
                for (int i = 0; i < 4; ++i)
                    #pragma unroll
                    for (int o = 0; o < 2; ++o) {
                        union { ull u; float2 f; } u; u.u = acc[g][i][o];
                        p[(g*4 + i)*2 + o] = u.f.x + u.f.y;
                    }
            #pragma unroll
            for (int s = 0; s < 24; ++s)
                p[s] += __shfl_xor_sync(0xffffffffu, p[s], 16);

            if (lane < 16) {
                float* R = Racc + (warp * 16 + jj) * 24;
                #pragma unroll
                for (int s = 0; s < 24; ++s) R[s] = p[s];
            }
        }
        __syncthreads();

        // Reconcile 4 ksh partials for this thread's single output (gb, j)
        {
            const int jjr = col >> 1;
            const int o   = col & 1;
            const int ib  = eb & 3;
            const int bbr = eb >> 2;
            float hg[3];
            #pragma unroll
            for (int g = 0; g < 3; ++g) {
                const int slot = (g*4 + ib)*2 + o;
                hg[g] = Racc[(((0*4 + bbr)*16 + jjr))*24 + slot]
                      + Racc[(((1*4 + bbr)*16 + jjr))*24 + slot]
                      + Racc[(((2*4 + bbr)*16 + jjr))*24 + slot]
                      + Racc[(((3*4 + bbr)*16 + jjr))*24 + slot];
            }
            const float r = sigmoidf_(xr + hg[0] + bhr);
            const float z = sigmoidf_(xz + hg[1] + bhz);
            const float n = tanhf(xn + r * (hg[2] + bhn));
            hdst[(size_t)gb * HID + j] = (1.0f - z) * n + z * hp;
        }

        group_barrier_(bg);
    }
}

// ---------------------------------------------------------------------------
// Kernel 4: per-(t,b) loss for t>=1.
// ---------------------------------------------------------------------------
__global__ void loss_kernel(const float* __restrict__ x,
                            const float* __restrict__ tin,
                            const float* __restrict__ mask,
                            const float* __restrict__ W_he,
                            const float* __restrict__ b_he,
                            const float* __restrict__ W_mu,
                            const float* __restrict__ b_mu,
                            const float* __restrict__ W_lv,
                            const float* __restrict__ b_lv,
                            const float* __restrict__ h_inf,
                            const float* __restrict__ t_inf,
                            const float* __restrict__ b_int) {
    __shared__ float Hs[8][HID];
    __shared__ float Ws[SDIM][17];
    __shared__ float He[8][SDIM];
    __shared__ float red[8][32];

    const int tid    = threadIdx.x;    // 256
    const int r_base = BATCH + blockIdx.x * 8;

    for (int i = tid; i < 8 * HID; i += 256) {
        int rr = i >> 9, k = i & (HID - 1);
        Hs[rr][k] = g_hs[(size_t)(r_base + rr) * HID + k];
    }
    __syncthreads();

    const int s    = tid & 127;
    const int rgrp = tid >> 7;
    float acc[4] = {0.f, 0.f, 0.f, 0.f};

    for (int kc = 0; kc < HID; kc += 16) {
        for (int i = tid; i < SDIM * 16; i += 256) {
            int s2 = i >> 4, k = i & 15;
            Ws[s2][k] = W_he[(size_t)s2 * HID + kc + k];
        }
        __syncthreads();
        #pragma unroll
        for (int k = 0; k < 16; ++k) {
            float w = Ws[s][k];
            #pragma unroll
            for (int q = 0; q < 4; ++q)
                acc[q] += Hs[rgrp + 2*q][kc + k] * w;
        }
        __syncthreads();
    }
    {
        const float bs = b_he[s];
        #pragma unroll
        for (int q = 0; q < 4; ++q)
            He[rgrp + 2*q][s] = fmaxf(acc[q] + bs, 0.0f);
    }
    __syncthreads();

    if (tid < 8 * MDIM) {
        const int r = tid / MDIM;
        const int m = tid % MDIM;
        float mu = b_mu[m];
        float lv = b_lv[m];
        #pragma unroll 4
        for (int k = 0; k < SDIM; ++k) {
            const float he = He[r][k];
            mu += W_mu[m * SDIM + k] * he;
            lv += W_lv[m * SDIM + k] * he;
        }
        const float sigma = fmaxf(expf(0.5f * lv), SIGMA_MIN);
        const float xv = x[(size_t)(r_base + r) * MDIM + m];
        const float d = (xv - mu) / sigma;
        red[r][m] = -0.5f * d * d - logf(sigma) - 0.5f * LOG2PI;
    }
    __syncthreads();

    if (tid < 8) {
        const int r = tid;
        float marker_ll = 0.0f;
        for (int m = 0; m < MDIM; ++m) marker_ll += red[r][m];

        float past = 0.0f;
        for (int k = 0; k < SDIM; ++k) past += He[r][k] * h_inf[k];

        const float ti = t_inf[0];
        const float bi = b_int[0];
        const float tg = tin[(size_t)(r_base + r) * 2 + 1];
        const float term1 = past + ti * tg + bi;
        const float time_ll = term1 + (expf(past + bi) - expf(term1)) / ti;

        const int row = r_base + r;
        g_loss[row] = (GAMMA * (-time_ll) + (-marker_ll)) * mask[row];
    }
}

// ---------------------------------------------------------------------------
// Kernel 5a/5b: deterministic two-stage reduction (double accumulation)
// ---------------------------------------------------------------------------
__global__ void reduce1_kernel() {
    __shared__ double sd[256];
    const int tid = threadIdx.x;
    double sum = 0.0;
    for (int i = BATCH + blockIdx.x * 256 + tid; i < TB; i += 64 * 256)
        sum += (double)g_loss[i];
    sd[tid] = sum;
    __syncthreads();
    for (int off = 128; off > 0; off >>= 1) {
        if (tid < off) sd[tid] += sd[tid + off];
        __syncthreads();
    }
    if (tid == 0) g_partial[blockIdx.x] = sd[0];
}

__global__ void reduce2_kernel(float* __restrict__ out) {
    __shared__ double sd[64];
    const int tid = threadIdx.x;   // 64
    sd[tid] = g_partial[tid];
    __syncthreads();
    for (int off = 32; off > 0; off >>= 1) {
        if (tid < off) sd[tid] += sd[tid + off];
        __syncthreads();
    }
    if (tid == 0) out[0] = (float)sd[0];
}

// ---------------------------------------------------------------------------
extern "C" void kernel_launch(void* const* d_in, const int* in_sizes, int n_in,
                              void* d_out, int out_size) {
    (void)in_sizes; (void)n_in; (void)out_size;
    const float* x       = (const float*)d_in[0];
    const float* tin     = (const float*)d_in[1];
    const float* mask    = (const float*)d_in[2];
    const float* W_embed = (const float*)d_in[3];
    const float* b_embed = (const float*)d_in[4];
    const float* W_ih    = (const float*)d_in[5];
    const float* b_ih    = (const float*)d_in[6];
    const float* W_hh    = (const float*)d_in[7];
    const float* b_hh    = (const float*)d_in[8];
    const float* W_he    = (const float*)d_in[9];
    const float* b_he    = (const float*)d_in[10];
    const float* W_mu    = (const float*)d_in[11];
    const float* b_mu    = (const float*)d_in[12];
    const float* W_lv    = (const float*)d_in[13];
    const float* b_lv    = (const float*)d_in[14];
    const float* h_inf   = (const float*)d_in[15];
    const float* t_inf   = (const float*)d_in[16];
    const float* b_int   = (const float*)d_in[17];
    float* out = (float*)d_out;

    cudaFuncSetAttribute(gru_persistent_kernel,
                         cudaFuncAttributeMaxDynamicSharedMemorySize,
                         GRU_SMEM_BYTES);

    zero_h0_kernel<<<64, 1024>>>();
    phi_kernel<<<TB / 16, 256>>>(x, W_embed, b_embed);
    xg_kernel<<<dim3(G3 / 128, TB / 128), 256>>>(W_ih, b_ih);
    gru_persistent_kernel<<<128, 512, GRU_SMEM_BYTES>>>(W_hh, b_hh);
    loss_kernel<<<(TB - BATCH) / 8, 256>>>(x, tin, mask, W_he, b_he,
                                           W_mu, b_mu, W_lv, b_lv,
                                           h_inf, t_inf, b_int);
    reduce1_kernel<<<64, 256>>>();
    reduce2_kernel<<<1, 64>>>(out);
}

// round 14
// speedup vs baseline: 1.5806x; 1.0159x over previous
#include <cuda_runtime.h>
#include <math.h>
#include <stdint.h>

// Problem constants (fixed shapes from reference setup_inputs)
#define T_STEPS 512
#define BATCH   128
#define MDIM    31
#define HID     512
#define EMB     256
#define SDIM    128
#define G3      (3*HID)          // 1536
#define TB      (T_STEPS*BATCH)  // 65536
#define BH      (BATCH*HID)      // 65536

#define SIGMA_MIN 0.01f
#define GAMMA     1.0f
#define LOG2PI    1.8378770664093453f

typedef unsigned long long ull;

// Scratch (device globals: no allocations allowed)
__device__ float g_phi[TB*EMB];                 //  67 MB
__device__ float g_xg [(size_t)TB*G3];          // 402 MB
__device__ float g_hs [(size_t)TB*HID];         // 134 MB  (hs[t] = h_t; hs[0]=0)
__device__ float g_loss[TB];                    // per-(t,b) loss, t>=1 written
__device__ double g_partial[64];                // reduction partials

// per-group barrier state (8 groups, 128B apart; gen monotonic across replays)
__device__ unsigned g_gcnt[8*32];
__device__ unsigned g_ggen[8*32];

__device__ __forceinline__ float sigmoidf_(float v) {
    return 1.0f / (1.0f + expf(-v));
}

// packed fp32x2 ops (Blackwell f32x2 pipe)
__device__ __forceinline__ ull ffma2_(ull a, ull b, ull c) {
    ull d;
    asm("fma.rn.f32x2 %0, %1, %2, %3;" : "=l"(d) : "l"(a), "l"(b), "l"(c));
    return d;
}

__device__ __forceinline__ void cp_async16(uint32_t dst, const void* src) {
    asm volatile("cp.async.ca.shared.global [%0], [%1], 16;" :: "r"(dst), "l"(src));
}

// ---------------------------------------------------------------------------
// Kernel 0: zero h_0
// ---------------------------------------------------------------------------
__global__ void zero_h0_kernel() {
    int i = blockIdx.x * blockDim.x + threadIdx.x;
    if (i < BH) g_hs[i] = 0.0f;
}

// ---------------------------------------------------------------------------
// Kernel 1: phi = relu(x @ W_embed^T + b_embed)   [TB,31] -> [TB,256]
// ---------------------------------------------------------------------------
__global__ void phi_kernel(const float* __restrict__ x,
                           const float* __restrict__ W_embed,
                           const float* __restrict__ b_embed) {
    __shared__ float Ws[EMB * MDIM];
    __shared__ float Xs[16 * MDIM];

    const int tid  = threadIdx.x;      // 256 threads
    const int row0 = blockIdx.x * 16;

    for (int i = tid; i < EMB * MDIM; i += 256) Ws[i] = W_embed[i];
    for (int i = tid; i < 16 * MDIM;  i += 256) Xs[i] = x[row0 * MDIM + i];
    __syncthreads();

    const int e = tid;
    const float be = b_embed[e];
    #pragma unroll 4
    for (int r = 0; r < 16; ++r) {
        float acc = be;
        #pragma unroll
        for (int k = 0; k < MDIM; ++k)
            acc += Xs[r * MDIM + k] * Ws[e * MDIM + k];
        g_phi[(row0 + r) * EMB + e] = fmaxf(acc, 0.0f);
    }
}

// ---------------------------------------------------------------------------
// Kernel 2: x_gates = phi @ W_ih^T + b_ih   [TB,256] x [1536,256] -> [TB,1536]
// 128x128x16 tile, 256 threads, 8x8 microtile, packed f32x2 FMAs (k-pairs).
// ---------------------------------------------------------------------------
__global__ __launch_bounds__(256, 1)
void xg_kernel(const float* __restrict__ W_ih,
               const float* __restrict__ b_ih) {
    __shared__ float As[128][18];      // phi rows (M), k-major, padded
    __shared__ float Bs[128][18];      // W_ih rows (N), k-major, padded

    const int tid = threadIdx.x;       // 256
    const int tx = tid & 15;
    const int ty = tid >> 4;
    const int n0 = blockIdx.x * 128;   // over G3 (12 tiles)
    const int m0 = blockIdx.y * 128;   // over TB (512 tiles)

    ull c2[8][8];
    #pragma unroll
    for (int i = 0; i < 8; ++i)
        #pragma unroll
        for (int j = 0; j < 8; ++j) c2[i][j] = 0ull;

    for (int kc = 0; kc < EMB; kc += 16) {
        #pragma unroll
        for (int v = 0; v < 2; ++v) {
            const int idx = tid + v * 256;       // 0..511
            const int row = idx >> 2;
            const int col = (idx & 3) * 4;
            float4 a = *reinterpret_cast<const float4*>(
                &g_phi[(size_t)(m0 + row) * EMB + kc + col]);
            float4 b = *reinterpret_cast<const float4*>(
                &W_ih[(size_t)(n0 + row) * EMB + kc + col]);
            As[row][col+0] = a.x; As[row][col+1] = a.y;
            As[row][col+2] = a.z; As[row][col+3] = a.w;
            Bs[row][col+0] = b.x; Bs[row][col+1] = b.y;
            Bs[row][col+2] = b.z; Bs[row][col+3] = b.w;
        }
        __syncthreads();

        #pragma unroll
        for (int kp = 0; kp < 8; ++kp) {
            ull a[8], b[8];
            #pragma unroll
            for (int i = 0; i < 8; ++i)
                a[i] = *reinterpret_cast<const ull*>(&As[ty*8 + i][2*kp]);
            #pragma unroll
            for (int j = 0; j < 8; ++j)
                b[j] = *reinterpret_cast<const ull*>(&Bs[tx*8 + j][2*kp]);
            #pragma unroll
            for (int i = 0; i < 8; ++i)
                #pragma unroll
                for (int j = 0; j < 8; ++j)
                    c2[i][j] = ffma2_(a[i], b[j], c2[i][j]);
        }
        __syncthreads();
    }

    // Epilogue: collapse k-pair lanes, add bias, store
    float bias[8];
    #pragma unroll
    for (int j = 0; j < 8; ++j) bias[j] = b_ih[n0 + tx*8 + j];

    #pragma unroll
    for (int i = 0; i < 8; ++i) {
        const int m = m0 + ty*8 + i;
        float v[8];
        #pragma unroll
        for (int j = 0; j < 8; ++j) {
            union { ull u; float2 f; } u; u.u = c2[i][j];
            v[j] = u.f.x + u.f.y + bias[j];
        }
        float4* dst = reinterpret_cast<float4*>(&g_xg[(size_t)m * G3 + n0 + tx*8]);
        dst[0] = make_float4(v[0], v[1], v[2], v[3]);
        dst[1] = make_float4(v[4], v[5], v[6], v[7]);
    }
}

// ---------------------------------------------------------------------------
// Kernel 3: PERSISTENT GRU, 2-D split, 512 threads (4 warps/SMSP).
// 128 CTAs = 16 jg x 8 bg. CTA (jg,bg): j in [32*jg,+32) x3 gates (96 W rows,
// smem-resident, loaded once) and batch rows [16*bg,+16).
// W layout: row-stride 514 floats (even -> aligned LDS.64). Thread jj handles
// j-cols {jj, jj+16}: half-warp W banks = 2*jj -> all 32 banks once, and the
// +16-row offset (16*514 == 0 mod 32) preserves the pattern. No swizzle ALU.
// Per step: 32 KB h-slice via cp.async16; 8-way k-split FFMA2 GEMM; in-warp
// shfl_xor(16) pair-reduce; smem Racc (aliases dead Hs) for the 4 ksh
// partials; 1 output/thread epilogue with register-carried h_prev and
// next-step xg prefetched under the GEMM. Acquire/release 16-CTA barriers
// (8 independent groups), no full membars.
// ---------------------------------------------------------------------------
#define PADH 516       // even (8B ok), 516*4 % 16 == 0 (cp.async16 ok)
#define WSTR 514       // W row stride (floats)
#define W_FLOATS (96*WSTR)                 // 49344 floats = 197376 B
#define H_FLOATS (16*PADH)                 //  8256 floats =  33024 B
#define GRU_SMEM_BYTES ((W_FLOATS + H_FLOATS)*4)   // 230400 <= 232448

__device__ __forceinline__ void group_barrier_(int grp) {
    __syncthreads();
    if (threadIdx.x == 0) {
        unsigned* cnt = &g_gcnt[grp * 32];
        unsigned* gen = &g_ggen[grp * 32];
        unsigned my_gen;
        asm volatile("ld.relaxed.gpu.global.u32 %0, [%1];"
                     : "=r"(my_gen) : "l"(gen));
        unsigned old;
        asm volatile("atom.acq_rel.gpu.global.add.u32 %0, [%1], 1;"
                     : "=r"(old) : "l"(cnt));
        if (old == 15u) {
            asm volatile("st.relaxed.gpu.global.u32 [%0], 0;" :: "l"(cnt));
            asm volatile("st.release.gpu.global.u32 [%0], %1;"
                         :: "l"(gen), "r"(my_gen + 1));
        } else {
            unsigned g;
            do {
                asm volatile("ld.acquire.gpu.global.u32 %0, [%1];"
                             : "=r"(g) : "l"(gen));
            } while (g == my_gen);
        }
    }
    __syncthreads();
}

__global__ __launch_bounds__(512, 1)
void gru_persistent_kernel(const float* __restrict__ W_hh,
                           const float* __restrict__ b_hh) {
    extern __shared__ float smem[];
    float* Ws = smem;                  // [96][WSTR]
    float* Hs = smem + W_FLOATS;       // [16][PADH]
    float* Racc = Hs;                  // aliases Hs: 16w x 16jj x 24 floats

    const int tid  = threadIdx.x;      // 512
    const int lane = tid & 31;
    const int warp = tid >> 5;         // 0..15
    const int bg   = blockIdx.x >> 4;  // 0..7   batch group
    const int jg   = blockIdx.x & 15;  // 0..15  j group

    // compute mapping
    const int jj  = lane & 15;         // j cols: jj and jj+16 (local)
    const int bb  = warp & 3;          // 4 b-rows: bb*4 .. bb*4+3
    const int ksh = warp >> 2;         // high k-split bits
    const int ks  = ksh * 2 + (lane >> 4);   // 0..7, k-range [ks*64,+64)

    // epilogue mapping: 1 output per thread
    const int eb  = tid >> 5;          // local batch row 0..15
    const int col = tid & 31;          // local j col 0..31
    const int j   = jg * 32 + col;
    const int gb  = bg * 16 + eb;

    // Load this CTA's W_hh slice once (row-stride WSTR, no swizzle).
    for (int i = tid; i < 96 * HID; i += 512) {
        const int wr = i >> 9, k = i & (HID - 1);
        const int g = wr >> 5, jl = wr & 31;
        Ws[wr * WSTR + k] = W_hh[((size_t)(g * HID + jg * 32 + jl)) * HID + k];
    }

    const float bhr = b_hh[j];
    const float bhz = b_hh[HID + j];
    const float bhn = b_hh[2*HID + j];
    __syncthreads();

    const uint32_t hs_base = (uint32_t)__cvta_generic_to_shared(Hs);
    const int cr = tid >> 5;           // copy: row 0..15
    const int cc = tid & 31;           // copy: 16B chunk phase

    // inner-loop thread-invariant base pointers
    const float* Hbase = Hs + bb * 4 * PADH + ks * 64;
    const float* Wr0 = Ws + (0*32 + jj) * WSTR + ks * 64;
    const float* Wr1 = Wr0 + 16 * WSTR;
    const float* Wz0 = Ws + (1*32 + jj) * WSTR + ks * 64;
    const float* Wz1 = Wz0 + 16 * WSTR;
    const float* Wn0 = Ws + (2*32 + jj) * WSTR + ks * 64;
    const float* Wn1 = Wn0 + 16 * WSTR;

    // register-carried state: h_prev for this thread's (gb, j); h0 = 0
    float hp = 0.0f;
    // xg for step 0
    float xr = g_xg[(size_t)gb * G3 + j];
    float xz = g_xg[(size_t)gb * G3 + HID + j];
    float xn = g_xg[(size_t)gb * G3 + 2*HID + j];

    for (int t = 0; t < T_STEPS - 1; ++t) {
        const float* __restrict__ hsrc = g_hs + (size_t)t * BH;
        float*       __restrict__ hdst = g_hs + (size_t)(t + 1) * BH;
        const float* __restrict__ xgn  = g_xg + (size_t)(t + 1) * BATCH * G3;

        // Load the 16x512 h-slice for this bg (32 KB, 4x cp.async16/thread)
        {
            const float* src = hsrc + (size_t)(bg * 16 + cr) * HID + cc * 4;
            uint32_t dst = hs_base + (uint32_t)(cr * PADH + cc * 4) * 4u;
            #pragma unroll
            for (int it = 0; it < 4; ++it) {
                cp_async16(dst, src);
                src += 128;
                dst += 512;
            }
            asm volatile("cp.async.commit_group;");
        }

        // Prefetch next step's xg (DRAM latency hidden under h-load + GEMM)
        const float xr_n = xgn[(size_t)gb * G3 + j];
        const float xz_n = xgn[(size_t)gb * G3 + HID + j];
        const float xn_n = xgn[(size_t)gb * G3 + 2*HID + j];

        ull acc[3][4][2];
        #pragma unroll
        for (int g = 0; g < 3; ++g)
            #pragma unroll
            for (int i = 0; i < 4; ++i) { acc[g][i][0] = 0ull; acc[g][i][1] = 0ull; }

        asm volatile("cp.async.wait_group 0;");
        __syncthreads();

        // GEMM: 4 b-rows x 2 j x 3 gates over k-range [ks*64, +64) (32 kp)
        #pragma unroll 8
        for (int kpl = 0; kpl < 32; ++kpl) {
            const int kk = 2 * kpl;
            ull h[4];
            #pragma unroll
            for (int i = 0; i < 4; ++i)
                h[i] = *reinterpret_cast<const ull*>(Hbase + i * PADH + kk);
            {
                const ull w0 = *reinterpret_cast<const ull*>(Wr0 + kk);
                const ull w1 = *reinterpret_cast<const ull*>(Wr1 + kk);
                #pragma unroll
                for (int i = 0; i < 4; ++i) {
                    acc[0][i][0] = ffma2_(h[i], w0, acc[0][i][0]);
                    acc[0][i][1] = ffma2_(h[i], w1, acc[0][i][1]);
                }
            }
            {
                const ull w0 = *reinterpret_cast<const ull*>(Wz0 + kk);
                const ull w1 = *reinterpret_cast<const ull*>(Wz1 + kk);
                #pragma unroll
                for (int i = 0; i < 4; ++i) {
                    acc[1][i][0] = ffma2_(h[i], w0, acc[1][i][0]);
                    acc[1][i][1] = ffma2_(h[i], w1, acc[1][i][1]);
                }
            }
            {
                const ull w0 = *reinterpret_cast<const ull*>(Wn0 + kk);
                const ull w1 = *reinterpret_cast<const ull*>(Wn1 + kk);
                #pragma unroll
                for (int i = 0; i < 4; ++i) {
                    acc[2][i][0] = ffma2_(h[i], w0, acc[2][i][0]);
                    acc[2][i][1] = ffma2_(h[i], w1, acc[2][i][1]);
                }
            }
        }
        __syncthreads();   // h reads done; Hs region now reusable as Racc

        // Collapse f32x2 lanes, reduce the in-warp ksl pair via shfl_xor(16),
        // publish from lanes < 16. Slot order: (g*4+i)*2+o, o = col-half.
        {
            float p[24];
            #pragma unroll
            for (int g = 0; g < 3; ++g)
                #pragma unroll
                for (int i = 0; i < 4; ++i)
                    #pragma unroll
                    for (int o = 0; o < 2; ++o) {
                        union { ull u; float2 f; } u; u.u = acc[g][i][o];
                        p[(g*4 + i)*2 + o] = u.f.x + u.f.y;
                    }
            #pragma unroll
            for (int s = 0; s < 24; ++s)
                p[s] += __shfl_xor_sync(0xffffffffu, p[s], 16);

            if (lane < 16) {
                float* R = Racc + (warp * 16 + jj) * 24;
                #pragma unroll
                for (int s = 0; s < 24; ++s) R[s] = p[s];
            }
        }
        __syncthreads();

        // Reconcile 4 ksh partials for this thread's single output (gb, j)
        {
            const int jjr = col & 15;
            const int o   = col >> 4;
            const int ib  = eb & 3;
            const int bbr = eb >> 2;
            float hg[3];
            #pragma unroll
            for (int g = 0; g < 3; ++g) {
                const int slot = (g*4 + ib)*2 + o;
                hg[g] = Racc[(((0*4 + bbr)*16 + jjr))*24 + slot]
                      + Racc[(((1*4 + bbr)*16 + jjr))*24 + slot]
                      + Racc[(((2*4 + bbr)*16 + jjr))*24 + slot]
                      + Racc[(((3*4 + bbr)*16 + jjr))*24 + slot];
            }
            const float r = sigmoidf_(xr + hg[0] + bhr);
            const float z = sigmoidf_(xz + hg[1] + bhz);
            const float n = tanhf(xn + r * (hg[2] + bhn));
            const float hnew = (1.0f - z) * n + z * hp;
            hdst[(size_t)gb * HID + j] = hnew;
            hp = hnew;
        }

        xr = xr_n; xz = xz_n; xn = xn_n;

        group_barrier_(bg);
    }
}

// ---------------------------------------------------------------------------
// Kernel 4: per-(t,b) loss for t>=1.
// ---------------------------------------------------------------------------
__global__ void loss_kernel(const float* __restrict__ x,
                            const float* __restrict__ tin,
                            const float* __restrict__ mask,
                            const float* __restrict__ W_he,
                            const float* __restrict__ b_he,
                            const float* __restrict__ W_mu,
                            const float* __restrict__ b_mu,
                            const float* __restrict__ W_lv,
                            const float* __restrict__ b_lv,
                            const float* __restrict__ h_inf,
                            const float* __restrict__ t_inf,
                            const float* __restrict__ b_int) {
    __shared__ float Hs[8][HID];
    __shared__ float Ws[SDIM][17];
    __shared__ float He[8][SDIM];
    __shared__ float red[8][32];

    const int tid    = threadIdx.x;    // 256
    const int r_base = BATCH + blockIdx.x * 8;

    for (int i = tid; i < 8 * HID; i += 256) {
        int rr = i >> 9, k = i & (HID - 1);
        Hs[rr][k] = g_hs[(size_t)(r_base + rr) * HID + k];
    }
    __syncthreads();

    const int s    = tid & 127;
    const int rgrp = tid >> 7;
    float acc[4] = {0.f, 0.f, 0.f, 0.f};

    for (int kc = 0; kc < HID; kc += 16) {
        for (int i = tid; i < SDIM * 16; i += 256) {
            int s2 = i >> 4, k = i & 15;
            Ws[s2][k] = W_he[(size_t)s2 * HID + kc + k];
        }
        __syncthreads();
        #pragma unroll
        for (int k = 0; k < 16; ++k) {
            float w = Ws[s][k];
            #pragma unroll
            for (int q = 0; q < 4; ++q)
                acc[q] += Hs[rgrp + 2*q][kc + k] * w;
        }
        __syncthreads();
    }
    {
        const float bs = b_he[s];
        #pragma unroll
        for (int q = 0; q < 4; ++q)
            He[rgrp + 2*q][s] = fmaxf(acc[q] + bs, 0.0f);
    }
    __syncthreads();

    if (tid < 8 * MDIM) {
        const int r = tid / MDIM;
        const int m = tid % MDIM;
        float mu = b_mu[m];
        float lv = b_lv[m];
        #pragma unroll 4
        for (int k = 0; k < SDIM; ++k) {
            const float he = He[r][k];
            mu += W_mu[m * SDIM + k] * he;
            lv += W_lv[m * SDIM + k] * he;
        }
        const float sigma = fmaxf(expf(0.5f * lv), SIGMA_MIN);
        const float xv = x[(size_t)(r_base + r) * MDIM + m];
        const float d = (xv - mu) / sigma;
        red[r][m] = -0.5f * d * d - logf(sigma) - 0.5f * LOG2PI;
    }
    __syncthreads();

    if (tid < 8) {
        const int r = tid;
        float marker_ll = 0.0f;
        for (int m = 0; m < MDIM; ++m) marker_ll += red[r][m];

        float past = 0.0f;
        for (int k = 0; k < SDIM; ++k) past += He[r][k] * h_inf[k];

        const float ti = t_inf[0];
        const float bi = b_int[0];
        const float tg = tin[(size_t)(r_base + r) * 2 + 1];
        const float term1 = past + ti * tg + bi;
        const float time_ll = term1 + (expf(past + bi) - expf(term1)) / ti;

        const int row = r_base + r;
        g_loss[row] = (GAMMA * (-time_ll) + (-marker_ll)) * mask[row];
    }
}

// ---------------------------------------------------------------------------
// Kernel 5a/5b: deterministic two-stage reduction (double accumulation)
// ---------------------------------------------------------------------------
__global__ void reduce1_kernel() {
    __shared__ double sd[256];
    const int tid = threadIdx.x;
    double sum = 0.0;
    for (int i = BATCH + blockIdx.x * 256 + tid; i < TB; i += 64 * 256)
        sum += (double)g_loss[i];
    sd[tid] = sum;
    __syncthreads();
    for (int off = 128; off > 0; off >>= 1) {
        if (tid < off) sd[tid] += sd[tid + off];
        __syncthreads();
    }
    if (tid == 0) g_partial[blockIdx.x] = sd[0];
}

__global__ void reduce2_kernel(float* __restrict__ out) {
    __shared__ double sd[64];
    const int tid = threadIdx.x;   // 64
    sd[tid] = g_partial[tid];
    __syncthreads();
    for (int off = 32; off > 0; off >>= 1) {
        if (tid < off) sd[tid] += sd[tid + off];
        __syncthreads();
    }
    if (tid == 0) out[0] = (float)sd[0];
}

// ---------------------------------------------------------------------------
extern "C" void kernel_launch(void* const* d_in, const int* in_sizes, int n_in,
                              void* d_out, int out_size) {
    (void)in_sizes; (void)n_in; (void)out_size;
    const float* x       = (const float*)d_in[0];
    const float* tin     = (const float*)d_in[1];
    const float* mask    = (const float*)d_in[2];
    const float* W_embed = (const float*)d_in[3];
    const float* b_embed = (const float*)d_in[4];
    const float* W_ih    = (const float*)d_in[5];
    const float* b_ih    = (const float*)d_in[6];
    const float* W_hh    = (const float*)d_in[7];
    const float* b_hh    = (const float*)d_in[8];
    const float* W_he    = (const float*)d_in[9];
    const float* b_he    = (const float*)d_in[10];
    const float* W_mu    = (const float*)d_in[11];
    const float* b_mu    = (const float*)d_in[12];
    const float* W_lv    = (const float*)d_in[13];
    const float* b_lv    = (const float*)d_in[14];
    const float* h_inf   = (const float*)d_in[15];
    const float* t_inf   = (const float*)d_in[16];
    const float* b_int   = (const float*)d_in[17];
    float* out = (float*)d_out;

    cudaFuncSetAttribute(gru_persistent_kernel,
                         cudaFuncAttributeMaxDynamicSharedMemorySize,
                         GRU_SMEM_BYTES);

    zero_h0_kernel<<<64, 1024>>>();
    phi_kernel<<<TB / 16, 256>>>(x, W_embed, b_embed);
    xg_kernel<<<dim3(G3 / 128, TB / 128), 256>>>(W_ih, b_ih);
    gru_persistent_kernel<<<128, 512, GRU_SMEM_BYTES>>>(W_hh, b_hh);
    loss_kernel<<<(TB - BATCH) / 8, 256>>>(x, tin, mask, W_he, b_he,
                                           W_mu, b_mu, W_lv, b_lv,
                                           h_inf, t_inf, b_int);
    reduce1_kernel<<<64, 256>>>();
    reduce2_kernel<<<1, 64>>>(out);
}